// round 9
// baseline (speedup 1.0000x reference)
#include <cuda_runtime.h>
#include <cuda_bf16.h>
#include <math.h>
#include <stdint.h>

#define G_      128
#define NPG_    256
#define DIMM    512
#define HEADS_  8
#define DH_     64
#define NTOK    (G_*NPG_)                  // 32768
#define SBUF    ((size_t)NTOK * DIMM)      // 16,777,216 elems

// ---------------- scratch (device globals; total ~400 MB, matches passing R6) ----------------
__device__ float g_pool[3 * SBUF];
__device__ __nv_bfloat16 g_act[6 * SBUF];
#define WTOT 4194304
__device__ __nv_bfloat16 g_wt[2 * WTOT];

// ================= helpers =================
__device__ __forceinline__ uint32_t smem_u32(const void* p) {
    uint32_t a;
    asm("{ .reg .u64 t; cvta.to.shared.u64 t, %1; cvt.u32.u64 %0, t; }" : "=r"(a) : "l"(p));
    return a;
}
__device__ __forceinline__ void cp16(uint32_t dst, const void* src) {
    asm volatile("cp.async.cg.shared.global [%0], [%1], 16;" :: "r"(dst), "l"(src));
}
#define CP_COMMIT() asm volatile("cp.async.commit_group;")
#define CP_WAIT1()  asm volatile("cp.async.wait_group 1;")

__device__ __forceinline__ void ldsm4(uint32_t* r, uint32_t addr) {
    asm volatile("ldmatrix.sync.aligned.m8n8.x4.shared.b16 {%0,%1,%2,%3}, [%4];"
        : "=r"(r[0]), "=r"(r[1]), "=r"(r[2]), "=r"(r[3]) : "r"(addr));
}
__device__ __forceinline__ void ldsm4t(uint32_t* r, uint32_t addr) {
    asm volatile("ldmatrix.sync.aligned.m8n8.x4.trans.shared.b16 {%0,%1,%2,%3}, [%4];"
        : "=r"(r[0]), "=r"(r[1]), "=r"(r[2]), "=r"(r[3]) : "r"(addr));
}
__device__ __forceinline__ void mma16816(float* d, const uint32_t* a, const uint32_t* b) {
    asm volatile("mma.sync.aligned.m16n8k16.row.col.f32.bf16.bf16.f32 "
        "{%0,%1,%2,%3}, {%4,%5,%6,%7}, {%8,%9}, {%0,%1,%2,%3};"
        : "+f"(d[0]), "+f"(d[1]), "+f"(d[2]), "+f"(d[3])
        : "r"(a[0]), "r"(a[1]), "r"(a[2]), "r"(a[3]), "r"(b[0]), "r"(b[1]));
}
__device__ __forceinline__ void splitf(float x, __nv_bfloat16& h, __nv_bfloat16& l) {
    h = __float2bfloat16_rn(x);
    l = __float2bfloat16_rn(x - __bfloat162float(h));
}
__device__ __forceinline__ float gelu_f(float v) {
    return 0.5f * v * (1.f + erff(v * 0.70710678118654752f));
}

// ================= bf16x3 tensor-core GEMM (proven R6) =================
#define BM 128
#define BN 128
#define BK 32
#define A_PITCH 80
#define B_PITCH 272
#define A_BYTES (BM*A_PITCH)
#define B_BYTES (BK*B_PITCH)
#define STAGE_B (2*A_BYTES + 2*B_BYTES)
#define NSTG 3
#define GEMM_SMEM (NSTG*STAGE_B)

template<int EPI, int OUT>
__global__ __launch_bounds__(256, 2) void gemm_bf(
    const __nv_bfloat16* __restrict__ Ahi, const __nv_bfloat16* __restrict__ Alo,
    const __nv_bfloat16* __restrict__ Bhi, const __nv_bfloat16* __restrict__ Blo,
    const float* __restrict__ bias, const float* __restrict__ R,
    float* __restrict__ C, __nv_bfloat16* __restrict__ Chi, __nv_bfloat16* __restrict__ Clo,
    int M, int N, int K)
{
    extern __shared__ __align__(16) char sm[];
    const uint32_t sb = smem_u32(sm);
    const int tid = threadIdx.x;
    const int lane = tid & 31, warp = tid >> 5;
    const int wm = warp & 1, wn = warp >> 1;
    const int bm = blockIdx.y * BM, bn = blockIdx.x * BN;
    const int CCH = K / BK;

    float acc[4][4][4];
    #pragma unroll
    for (int a = 0; a < 4; a++)
        #pragma unroll
        for (int b = 0; b < 4; b++)
            #pragma unroll
            for (int k = 0; k < 4; k++) acc[a][b][k] = 0.f;

    #define ISSUE(cc_)  do {                                                       \
        const int c_ = (cc_);                                                      \
        if (c_ < CCH) {                                                            \
            const uint32_t st_ = sb + (c_ % NSTG) * STAGE_B;                       \
            const int k0_ = c_ * BK;                                               \
            _Pragma("unroll")                                                      \
            for (int i = 0; i < 4; i++) {                                          \
                int idx = tid + i * 256;                                           \
                int sel = idx >> 9, rem = idx & 511;                               \
                int row = rem >> 2, ch = rem & 3;                                  \
                const __nv_bfloat16* s = (sel ? Alo : Ahi)                         \
                    + (size_t)(bm + row) * K + k0_ + ch * 8;                       \
                cp16(st_ + sel * A_BYTES + row * A_PITCH + ch * 16, s);            \
            }                                                                      \
            _Pragma("unroll")                                                      \
            for (int i = 0; i < 4; i++) {                                          \
                int idx = tid + i * 256;                                           \
                int sel = idx >> 9, rem = idx & 511;                               \
                int kr = rem >> 4, ch = rem & 15;                                  \
                const __nv_bfloat16* s = (sel ? Blo : Bhi)                         \
                    + (size_t)(k0_ + kr) * N + bn + ch * 8;                        \
                cp16(st_ + 2 * A_BYTES + sel * B_BYTES + kr * B_PITCH + ch * 16, s);\
            }                                                                      \
        }                                                                          \
        CP_COMMIT();                                                               \
    } while (0)

    ISSUE(0);
    ISSUE(1);

    const int r8 = lane & 7, sub = lane >> 3;
    const int subr = (sub & 1) * 8, subc = sub >> 1;

    for (int c = 0; c < CCH; ++c) {
        CP_WAIT1();
        __syncthreads();
        ISSUE(c + 2);
        const uint32_t st = sb + (c % NSTG) * STAGE_B;
        #pragma unroll
        for (int ks = 0; ks < 2; ++ks) {
            uint32_t Af[4][4], Bh_[2][4], Bl_[2][4];
            #pragma unroll
            for (int mt = 0; mt < 4; mt++) {
                int row = wm * 64 + mt * 16 + r8 + subr;
                ldsm4(Af[mt], st + row * A_PITCH + ks * 32 + subc * 16);
            }
            #pragma unroll
            for (int p = 0; p < 2; p++) {
                int kr = ks * 16 + r8 + subr;
                int nc = wn * 32 + p * 16 + subc * 8;
                ldsm4t(Bh_[p], st + 2 * A_BYTES + kr * B_PITCH + nc * 2);
            }
            #pragma unroll
            for (int mt = 0; mt < 4; mt++)
                #pragma unroll
                for (int nt = 0; nt < 4; nt++)
                    mma16816(acc[mt][nt], Af[mt], &Bh_[nt >> 1][(nt & 1) * 2]);
            #pragma unroll
            for (int p = 0; p < 2; p++) {
                int kr = ks * 16 + r8 + subr;
                int nc = wn * 32 + p * 16 + subc * 8;
                ldsm4t(Bl_[p], st + 2 * A_BYTES + B_BYTES + kr * B_PITCH + nc * 2);
            }
            #pragma unroll
            for (int mt = 0; mt < 4; mt++)
                #pragma unroll
                for (int nt = 0; nt < 4; nt++)
                    mma16816(acc[mt][nt], Af[mt], &Bl_[nt >> 1][(nt & 1) * 2]);
            #pragma unroll
            for (int mt = 0; mt < 4; mt++) {
                int row = wm * 64 + mt * 16 + r8 + subr;
                ldsm4(Af[mt], st + A_BYTES + row * A_PITCH + ks * 32 + subc * 16);
            }
            #pragma unroll
            for (int mt = 0; mt < 4; mt++)
                #pragma unroll
                for (int nt = 0; nt < 4; nt++)
                    mma16816(acc[mt][nt], Af[mt], &Bh_[nt >> 1][(nt & 1) * 2]);
        }
    }

    const int g = lane >> 2, tq = lane & 3;
    #pragma unroll
    for (int mt = 0; mt < 4; mt++) {
        #pragma unroll
        for (int nt = 0; nt < 4; nt++) {
            const int row0 = bm + wm * 64 + mt * 16 + g;
            const int col  = bn + wn * 32 + nt * 8 + tq * 2;
            #pragma unroll
            for (int h2 = 0; h2 < 2; h2++) {
                const int r = row0 + h2 * 8;
                float v0 = acc[mt][nt][h2 * 2 + 0];
                float v1 = acc[mt][nt][h2 * 2 + 1];
                if (EPI >= 1) { v0 += bias[col]; v1 += bias[col + 1]; }
                if (EPI == 2) { v0 = gelu_f(v0); v1 = gelu_f(v1); }
                if (OUT >= 1) {
                    __nv_bfloat16 h0, l0, h1, l1;
                    splitf(v0, h0, l0); splitf(v1, h1, l1);
                    *(__nv_bfloat162*)(Chi + (size_t)r * N + col) = __nv_bfloat162(h0, h1);
                    *(__nv_bfloat162*)(Clo + (size_t)r * N + col) = __nv_bfloat162(l0, l1);
                }
                if (EPI == 3) {
                    const float2 rv = *(const float2*)(R + (size_t)r * N + col);
                    v0 += rv.x; v1 += rv.y;
                }
                if (OUT != 2)
                    *(float2*)(C + (size_t)r * N + col) = make_float2(v0, v1);
            }
        }
    }
    #undef ISSUE
}

// ================= fused weight split (1 launch replaces 8) =================
struct CvtArgs { const float* s[8]; };
__global__ __launch_bounds__(256) void cvt_all(
    CvtArgs a, __nv_bfloat16* __restrict__ wh, __nv_bfloat16* __restrict__ wl)
{
    int i = blockIdx.x * blockDim.x + threadIdx.x;   // float4 index, < 1048576
    int seg, off;
    if      (i <  65536) { seg = 0; off = 0; }
    else if (i < 196608) { seg = 1; off = 65536; }
    else if (i < 262144) { seg = 2; off = 196608; }
    else if (i < 327680) { seg = 3; off = 262144; }
    else if (i < 458752) { seg = 4; off = 327680; }
    else if (i < 524288) { seg = 5; off = 458752; }
    else if (i < 786432) { seg = 6; off = 524288; }
    else                 { seg = 7; off = 786432; }
    float4 v = ((const float4*)a.s[seg])[i - off];
    __nv_bfloat16 h0,l0,h1,l1,h2,l2,h3,l3;
    splitf(v.x,h0,l0); splitf(v.y,h1,l1); splitf(v.z,h2,l2); splitf(v.w,h3,l3);
    ((__nv_bfloat162*)wh)[i*2]   = __nv_bfloat162(h0,h1);
    ((__nv_bfloat162*)wh)[i*2+1] = __nv_bfloat162(h2,h3);
    ((__nv_bfloat162*)wl)[i*2]   = __nv_bfloat162(l0,l1);
    ((__nv_bfloat162*)wl)[i*2+1] = __nv_bfloat162(l2,l3);
}

// ================= group layernorm (proven R6) =================
template<int MODE>
__global__ __launch_bounds__(512) void group_ln_k(
    const float* __restrict__ x, const float* __restrict__ w, const float* __restrict__ b,
    float* __restrict__ y, __nv_bfloat16* __restrict__ yh, __nv_bfloat16* __restrict__ yl)
{
    const int g = blockIdx.x;
    const float4* xg = (const float4*)(x + (size_t)g * NPG_ * DIMM);
    const float4* w4 = (const float4*)w;
    const float4* b4 = (const float4*)b;
    const int per = NPG_ * DIMM / 4;

    float s = 0.f, s2 = 0.f;
    for (int i = threadIdx.x; i < per; i += 512) {
        float4 v = xg[i];
        s  += (v.x + v.y) + (v.z + v.w);
        s2 += (v.x*v.x + v.y*v.y) + (v.z*v.z + v.w*v.w);
    }
    __shared__ float rs[16], rs2[16];
    unsigned lane = threadIdx.x & 31, wid = threadIdx.x >> 5;
    #pragma unroll
    for (int o = 16; o; o >>= 1) {
        s  += __shfl_down_sync(0xFFFFFFFFu, s,  o);
        s2 += __shfl_down_sync(0xFFFFFFFFu, s2, o);
    }
    if (lane == 0) { rs[wid] = s; rs2[wid] = s2; }
    __syncthreads();
    __shared__ float sm_mean, sm_inv;
    if (threadIdx.x == 0) {
        float ts = 0.f, ts2 = 0.f;
        #pragma unroll
        for (int i = 0; i < 16; i++) { ts += rs[i]; ts2 += rs2[i]; }
        const float cnt = (float)(NPG_ * DIMM);
        float mean = ts / cnt;
        float var  = ts2 / cnt - mean * mean;
        sm_mean = mean;
        sm_inv  = rsqrtf(var + 1e-5f);
    }
    __syncthreads();
    const float mean = sm_mean, inv = sm_inv;
    float4*          yg  = MODE ? (float4*)(y + (size_t)g * NPG_ * DIMM) : nullptr;
    __nv_bfloat162*  yh2 = (__nv_bfloat162*)(yh + (size_t)g * NPG_ * DIMM);
    __nv_bfloat162*  yl2 = (__nv_bfloat162*)(yl + (size_t)g * NPG_ * DIMM);
    for (int i = threadIdx.x; i < per; i += 512) {
        float4 v = xg[i];
        float4 wv = w4[i & 127];
        float4 bv = b4[i & 127];
        float4 r;
        r.x = (v.x - mean) * inv * wv.x + bv.x;
        r.y = (v.y - mean) * inv * wv.y + bv.y;
        r.z = (v.z - mean) * inv * wv.z + bv.z;
        r.w = (v.w - mean) * inv * wv.w + bv.w;
        if (MODE) yg[i] = r;
        __nv_bfloat16 h0,l0,h1,l1,h2,l2,h3,l3;
        splitf(r.x,h0,l0); splitf(r.y,h1,l1); splitf(r.z,h2,l2); splitf(r.w,h3,l3);
        yh2[i*2]   = __nv_bfloat162(h0,h1);
        yh2[i*2+1] = __nv_bfloat162(h2,h3);
        yl2[i*2]   = __nv_bfloat162(l0,l1);
        yl2[i*2+1] = __nv_bfloat162(l2,l3);
    }
}

// ================= attention (SIMT fp32, proven R6) =================
__global__ __launch_bounds__(256) void attn_k(
    const float* __restrict__ qbuf, const float* __restrict__ kvbuf,
    __nv_bfloat16* __restrict__ oh, __nv_bfloat16* __restrict__ ol)
{
    __shared__ float Ks[64 * DH_];
    __shared__ float Vs[64 * DH_];
    const int g = blockIdx.x, h = blockIdx.y;
    const int i = threadIdx.x;
    const float* kvg = kvbuf + (size_t)g * NPG_ * 2 * DIMM;

    float q[DH_];
    {
        const float* qr = qbuf + ((size_t)(g * NPG_ + i)) * DIMM + h * DH_;
        #pragma unroll
        for (int d4 = 0; d4 < 16; d4++)
            *(float4*)(q + d4*4) = *(const float4*)(qr + d4*4);
    }
    float o[DH_];
    #pragma unroll
    for (int d = 0; d < DH_; d++) o[d] = 0.f;
    float m = -1e30f, l = 0.f;

    for (int jc = 0; jc < NPG_; jc += 64) {
        __syncthreads();
        for (int t = threadIdx.x; t < 64 * 16; t += 256) {
            int j = t >> 4, d4 = t & 15;
            const float* base = kvg + (size_t)(jc + j) * (2 * DIMM) + h * DH_;
            ((float4*)Ks)[t] = *(const float4*)(base + d4 * 4);
            ((float4*)Vs)[t] = *(const float4*)(base + DIMM + d4 * 4);
        }
        __syncthreads();

        for (int jj = 0; jj < 64; jj++) {
            const float4* kr = (const float4*)(Ks + jj * DH_);
            float sa0 = 0.f, sa1 = 0.f, sa2 = 0.f, sa3 = 0.f;
            #pragma unroll
            for (int d4 = 0; d4 < 16; d4 += 4) {
                float4 k0 = kr[d4+0], k1 = kr[d4+1], k2 = kr[d4+2], k3 = kr[d4+3];
                sa0 += q[(d4+0)*4+0]*k0.x + q[(d4+0)*4+1]*k0.y + q[(d4+0)*4+2]*k0.z + q[(d4+0)*4+3]*k0.w;
                sa1 += q[(d4+1)*4+0]*k1.x + q[(d4+1)*4+1]*k1.y + q[(d4+1)*4+2]*k1.z + q[(d4+1)*4+3]*k1.w;
                sa2 += q[(d4+2)*4+0]*k2.x + q[(d4+2)*4+1]*k2.y + q[(d4+2)*4+2]*k2.z + q[(d4+2)*4+3]*k2.w;
                sa3 += q[(d4+3)*4+0]*k3.x + q[(d4+3)*4+1]*k3.y + q[(d4+3)*4+2]*k3.z + q[(d4+3)*4+3]*k3.w;
            }
            float sc = ((sa0 + sa1) + (sa2 + sa3)) * 0.125f;

            float nm   = fmaxf(m, sc);
            float corr = __expf(m - nm);
            float p    = __expf(sc - nm);
            l = l * corr + p;
            const float4* vr = (const float4*)(Vs + jj * DH_);
            #pragma unroll
            for (int d4 = 0; d4 < 16; d4++) {
                float4 v4 = vr[d4];
                o[d4*4+0] = o[d4*4+0] * corr + p * v4.x;
                o[d4*4+1] = o[d4*4+1] * corr + p * v4.y;
                o[d4*4+2] = o[d4*4+2] * corr + p * v4.z;
                o[d4*4+3] = o[d4*4+3] * corr + p * v4.w;
            }
            m = nm;
        }
    }

    const float invl = 1.f / l;
    const size_t rb = ((size_t)(g * NPG_ + i)) * DIMM + h * DH_;
    __nv_bfloat162* oh2 = (__nv_bfloat162*)(oh + rb);
    __nv_bfloat162* ol2 = (__nv_bfloat162*)(ol + rb);
    #pragma unroll
    for (int d2 = 0; d2 < 32; d2++) {
        float v0 = o[d2*2+0] * invl, v1 = o[d2*2+1] * invl;
        __nv_bfloat16 h0,l0,h1,l1;
        splitf(v0,h0,l0); splitf(v1,h1,l1);
        oh2[d2] = __nv_bfloat162(h0,h1);
        ol2[d2] = __nv_bfloat162(l0,l1);
    }
}

// ================= launch =================
extern "C" void kernel_launch(void* const* d_in, const int* in_sizes, int n_in,
                              void* d_out, int out_size)
{
    (void)in_sizes; (void)n_in; (void)out_size;
    const float* x        = (const float*)d_in[0];
    const float* queries  = (const float*)d_in[1];
    const float* ln_seq_w = (const float*)d_in[3];
    const float* ln_seq_b = (const float*)d_in[4];
    const float* ln_q_w   = (const float*)d_in[5];
    const float* ln_q_b   = (const float*)d_in[6];
    const float* a1_Wq    = (const float*)d_in[7];
    const float* a1_Wkv   = (const float*)d_in[8];
    const float* a1_Wo    = (const float*)d_in[9];
    const float* a1_bo    = (const float*)d_in[10];
    const float* a2_Wq    = (const float*)d_in[11];
    const float* a2_Wkv   = (const float*)d_in[12];
    const float* a2_Wo    = (const float*)d_in[13];
    const float* a2_bo    = (const float*)d_in[14];
    const float* ff_ln_w  = (const float*)d_in[15];
    const float* ff_ln_b  = (const float*)d_in[16];
    const float* ff_W1    = (const float*)d_in[17];
    const float* ff_b1    = (const float*)d_in[18];
    const float* ff_W2    = (const float*)d_in[19];
    const float* ff_b2    = (const float*)d_in[20];

    float* out_x = (float*)d_out;
    float* out_q = out_x + SBUF;

    float* pool;  __nv_bfloat16* act;  __nv_bfloat16* wt;
    cudaGetSymbolAddress((void**)&pool, g_pool);
    cudaGetSymbolAddress((void**)&act,  g_act);
    cudaGetSymbolAddress((void**)&wt,   g_wt);

    float* p_q   = pool;                  // dead after attn2 -> x2
    float* p_kv  = pool + 1 * SBUF;       // dead after attn2 -> xn2
    float* p_x2  = pool;
    float* p_xn2 = pool + 1 * SBUF;

    __nv_bfloat16* xn_h = act + 0 * SBUF; __nv_bfloat16* xn_l = act + 1 * SBUF;
    __nv_bfloat16* qn_h = act + 2 * SBUF; __nv_bfloat16* qn_l = act + 3 * SBUF;
    __nv_bfloat16* o_h  = act + 2 * SBUF; __nv_bfloat16* o_l  = act + 3 * SBUF;  // overlay qn (dead)
    __nv_bfloat16* in_h = act + 4 * SBUF; __nv_bfloat16* in_l = act + 5 * SBUF;
    __nv_bfloat16* x2_h = act + 0 * SBUF; __nv_bfloat16* x2_l = act + 1 * SBUF;  // overlay xn (dead)
    __nv_bfloat16* h_h  = act + 2 * SBUF; __nv_bfloat16* h_l  = act + 4 * SBUF;  // half-token h pair

    const size_t OWQ1 = 0,        OWKV1 = 262144,  OWO1 = 786432;
    const size_t OWQ2 = 1048576,  OWKV2 = 1310720, OWO2 = 1835008;
    const size_t OW1  = 2097152,  OW2   = 3145728;
    __nv_bfloat16* wh = wt;  __nv_bfloat16* wl = wt + WTOT;

    cudaFuncSetAttribute(gemm_bf<0,0>, cudaFuncAttributeMaxDynamicSharedMemorySize, GEMM_SMEM);
    cudaFuncSetAttribute(gemm_bf<3,1>, cudaFuncAttributeMaxDynamicSharedMemorySize, GEMM_SMEM);
    cudaFuncSetAttribute(gemm_bf<2,2>, cudaFuncAttributeMaxDynamicSharedMemorySize, GEMM_SMEM);
    cudaFuncSetAttribute(gemm_bf<3,0>, cudaFuncAttributeMaxDynamicSharedMemorySize, GEMM_SMEM);

    CvtArgs ca;
    ca.s[0]=a1_Wq; ca.s[1]=a1_Wkv; ca.s[2]=a1_Wo; ca.s[3]=a2_Wq;
    ca.s[4]=a2_Wkv; ca.s[5]=a2_Wo; ca.s[6]=ff_W1; ca.s[7]=ff_W2;
    cvt_all<<<4096, 256>>>(ca, wh, wl);

    const dim3 gN512 (4,  NTOK/BM);      // (4, 256)
    const dim3 gN1024(8,  NTOK/BM);      // (8, 256)
    const dim3 attng(G_, HEADS_);

    group_ln_k<0><<<G_, 512>>>(x,       ln_seq_w, ln_seq_b, nullptr, xn_h, xn_l);
    group_ln_k<0><<<G_, 512>>>(queries, ln_q_w,   ln_q_b,   nullptr, qn_h, qn_l);

    // Attention 1: induced = attn(ln(queries), ln(x))
    gemm_bf<0,0><<<gN512,  256, GEMM_SMEM>>>(qn_h, qn_l, wh+OWQ1,  wl+OWQ1,  nullptr, nullptr,
                                             p_q,  nullptr, nullptr, NTOK, DIMM,   DIMM);
    gemm_bf<0,0><<<gN1024, 256, GEMM_SMEM>>>(xn_h, xn_l, wh+OWKV1, wl+OWKV1, nullptr, nullptr,
                                             p_kv, nullptr, nullptr, NTOK, 2*DIMM, DIMM);
    attn_k<<<attng, 256>>>(p_q, p_kv, o_h, o_l);
    // induced pair -> in_h/in_l ; q2 = induced + queries -> out_q (fused)
    gemm_bf<3,1><<<gN512,  256, GEMM_SMEM>>>(o_h, o_l, wh+OWO1, wl+OWO1, a1_bo, queries,
                                             out_q, in_h, in_l, NTOK, DIMM, DIMM);

    // Attention 2: out = attn(ln(x), induced); x2 = out + x (fused)
    gemm_bf<0,0><<<gN512,  256, GEMM_SMEM>>>(xn_h, xn_l, wh+OWQ2,  wl+OWQ2,  nullptr, nullptr,
                                             p_q,  nullptr, nullptr, NTOK, DIMM,   DIMM);
    gemm_bf<0,0><<<gN1024, 256, GEMM_SMEM>>>(in_h, in_l, wh+OWKV2, wl+OWKV2, nullptr, nullptr,
                                             p_kv, nullptr, nullptr, NTOK, 2*DIMM, DIMM);
    attn_k<<<attng, 256>>>(p_q, p_kv, o_h, o_l);
    gemm_bf<3,0><<<gN512,  256, GEMM_SMEM>>>(o_h, o_l, wh+OWO2, wl+OWO2, a2_bo, x,
                                             p_x2, nullptr, nullptr, NTOK, DIMM, DIMM);

    // FF block: LN, then two M-halves through the 4*SBUF-sized h pair buffer
    group_ln_k<1><<<G_, 512>>>(p_x2, ff_ln_w, ff_ln_b, p_xn2, x2_h, x2_l);

    const int MH = NTOK / 2;                       // 16384 rows per half
    const dim3 gFF1(4 * DIMM / BN, MH / BM);       // (16, 128)
    const dim3 gFF2(DIMM / BN,     MH / BM);       // (4, 128)
    for (int half = 0; half < 2; half++) {
        const size_t aoff = (size_t)half * MH * DIMM;
        gemm_bf<2,2><<<gFF1, 256, GEMM_SMEM>>>(x2_h + aoff, x2_l + aoff, wh+OW1, wl+OW1,
                                               ff_b1, nullptr,
                                               nullptr, h_h, h_l, MH, 4*DIMM, DIMM);
        gemm_bf<3,0><<<gFF2, 256, GEMM_SMEM>>>(h_h, h_l, wh+OW2, wl+OW2,
                                               ff_b2, p_xn2 + aoff,
                                               out_x + aoff, nullptr, nullptr,
                                               MH, DIMM, 4*DIMM);
    }
}

// round 13
// speedup vs baseline: 1.0958x; 1.0958x over previous
#include <cuda_runtime.h>
#include <cuda_bf16.h>
#include <math.h>
#include <stdint.h>

#define G_      128
#define NPG_    256
#define DIMM    512
#define HEADS_  8
#define DH_     64
#define NTOK    (G_*NPG_)                  // 32768
#define SBUF    ((size_t)NTOK * DIMM)      // 16,777,216 elems

// ---------------- scratch (identical decls to passing R9: ~400 MB) ----------------
__device__ float g_pool[3 * SBUF];
__device__ __nv_bfloat16 g_act[6 * SBUF];
#define WTOT 4194304
__device__ __nv_bfloat16 g_wt[2 * WTOT];

// ================= helpers =================
__device__ __forceinline__ uint32_t smem_u32(const void* p) {
    uint32_t a;
    asm("{ .reg .u64 t; cvta.to.shared.u64 t, %1; cvt.u32.u64 %0, t; }" : "=r"(a) : "l"(p));
    return a;
}
__device__ __forceinline__ void cp16(uint32_t dst, const void* src) {
    asm volatile("cp.async.cg.shared.global [%0], [%1], 16;" :: "r"(dst), "l"(src));
}
#define CP_COMMIT() asm volatile("cp.async.commit_group;")
#define CP_WAIT1()  asm volatile("cp.async.wait_group 1;")

__device__ __forceinline__ void ldsm4(uint32_t* r, uint32_t addr) {
    asm volatile("ldmatrix.sync.aligned.m8n8.x4.shared.b16 {%0,%1,%2,%3}, [%4];"
        : "=r"(r[0]), "=r"(r[1]), "=r"(r[2]), "=r"(r[3]) : "r"(addr));
}
__device__ __forceinline__ void ldsm4t(uint32_t* r, uint32_t addr) {
    asm volatile("ldmatrix.sync.aligned.m8n8.x4.trans.shared.b16 {%0,%1,%2,%3}, [%4];"
        : "=r"(r[0]), "=r"(r[1]), "=r"(r[2]), "=r"(r[3]) : "r"(addr));
}
__device__ __forceinline__ void mma16816(float* d, const uint32_t* a, const uint32_t* b) {
    asm volatile("mma.sync.aligned.m16n8k16.row.col.f32.bf16.bf16.f32 "
        "{%0,%1,%2,%3}, {%4,%5,%6,%7}, {%8,%9}, {%0,%1,%2,%3};"
        : "+f"(d[0]), "+f"(d[1]), "+f"(d[2]), "+f"(d[3])
        : "r"(a[0]), "r"(a[1]), "r"(a[2]), "r"(a[3]), "r"(b[0]), "r"(b[1]));
}
__device__ __forceinline__ void splitf(float x, __nv_bfloat16& h, __nv_bfloat16& l) {
    h = __float2bfloat16_rn(x);
    l = __float2bfloat16_rn(x - __bfloat162float(h));
}
__device__ __forceinline__ float gelu_f(float v) {
    return 0.5f * v * (1.f + erff(v * 0.70710678118654752f));
}

// ================= bf16x3 tensor-core GEMM (proven R6/R9) =================
#define BM 128
#define BN 128
#define BK 32
#define A_PITCH 80
#define B_PITCH 272
#define A_BYTES (BM*A_PITCH)
#define B_BYTES (BK*B_PITCH)
#define STAGE_B (2*A_BYTES + 2*B_BYTES)
#define NSTG 3
#define GEMM_SMEM (NSTG*STAGE_B)

template<int EPI, int OUT>
__global__ __launch_bounds__(256, 2) void gemm_bf(
    const __nv_bfloat16* __restrict__ Ahi, const __nv_bfloat16* __restrict__ Alo,
    const __nv_bfloat16* __restrict__ Bhi, const __nv_bfloat16* __restrict__ Blo,
    const float* __restrict__ bias, const float* __restrict__ R,
    float* __restrict__ C, __nv_bfloat16* __restrict__ Chi, __nv_bfloat16* __restrict__ Clo,
    int M, int N, int K)
{
    extern __shared__ __align__(16) char sm[];
    const uint32_t sb = smem_u32(sm);
    const int tid = threadIdx.x;
    const int lane = tid & 31, warp = tid >> 5;
    const int wm = warp & 1, wn = warp >> 1;
    const int bm = blockIdx.y * BM, bn = blockIdx.x * BN;
    const int CCH = K / BK;

    float acc[4][4][4];
    #pragma unroll
    for (int a = 0; a < 4; a++)
        #pragma unroll
        for (int b = 0; b < 4; b++)
            #pragma unroll
            for (int k = 0; k < 4; k++) acc[a][b][k] = 0.f;

    #define ISSUE(cc_)  do {                                                       \
        const int c_ = (cc_);                                                      \
        if (c_ < CCH) {                                                            \
            const uint32_t st_ = sb + (c_ % NSTG) * STAGE_B;                       \
            const int k0_ = c_ * BK;                                               \
            _Pragma("unroll")                                                      \
            for (int i = 0; i < 4; i++) {                                          \
                int idx = tid + i * 256;                                           \
                int sel = idx >> 9, rem = idx & 511;                               \
                int row = rem >> 2, ch = rem & 3;                                  \
                const __nv_bfloat16* s = (sel ? Alo : Ahi)                         \
                    + (size_t)(bm + row) * K + k0_ + ch * 8;                       \
                cp16(st_ + sel * A_BYTES + row * A_PITCH + ch * 16, s);            \
            }                                                                      \
            _Pragma("unroll")                                                      \
            for (int i = 0; i < 4; i++) {                                          \
                int idx = tid + i * 256;                                           \
                int sel = idx >> 9, rem = idx & 511;                               \
                int kr = rem >> 4, ch = rem & 15;                                  \
                const __nv_bfloat16* s = (sel ? Blo : Bhi)                         \
                    + (size_t)(k0_ + kr) * N + bn + ch * 8;                        \
                cp16(st_ + 2 * A_BYTES + sel * B_BYTES + kr * B_PITCH + ch * 16, s);\
            }                                                                      \
        }                                                                          \
        CP_COMMIT();                                                               \
    } while (0)

    ISSUE(0);
    ISSUE(1);

    const int r8 = lane & 7, sub = lane >> 3;
    const int subr = (sub & 1) * 8, subc = sub >> 1;

    for (int c = 0; c < CCH; ++c) {
        CP_WAIT1();
        __syncthreads();
        ISSUE(c + 2);
        const uint32_t st = sb + (c % NSTG) * STAGE_B;
        #pragma unroll
        for (int ks = 0; ks < 2; ++ks) {
            uint32_t Af[4][4], Bh_[2][4], Bl_[2][4];
            #pragma unroll
            for (int mt = 0; mt < 4; mt++) {
                int row = wm * 64 + mt * 16 + r8 + subr;
                ldsm4(Af[mt], st + row * A_PITCH + ks * 32 + subc * 16);
            }
            #pragma unroll
            for (int p = 0; p < 2; p++) {
                int kr = ks * 16 + r8 + subr;
                int nc = wn * 32 + p * 16 + subc * 8;
                ldsm4t(Bh_[p], st + 2 * A_BYTES + kr * B_PITCH + nc * 2);
            }
            #pragma unroll
            for (int mt = 0; mt < 4; mt++)
                #pragma unroll
                for (int nt = 0; nt < 4; nt++)
                    mma16816(acc[mt][nt], Af[mt], &Bh_[nt >> 1][(nt & 1) * 2]);
            #pragma unroll
            for (int p = 0; p < 2; p++) {
                int kr = ks * 16 + r8 + subr;
                int nc = wn * 32 + p * 16 + subc * 8;
                ldsm4t(Bl_[p], st + 2 * A_BYTES + B_BYTES + kr * B_PITCH + nc * 2);
            }
            #pragma unroll
            for (int mt = 0; mt < 4; mt++)
                #pragma unroll
                for (int nt = 0; nt < 4; nt++)
                    mma16816(acc[mt][nt], Af[mt], &Bl_[nt >> 1][(nt & 1) * 2]);
            #pragma unroll
            for (int mt = 0; mt < 4; mt++) {
                int row = wm * 64 + mt * 16 + r8 + subr;
                ldsm4(Af[mt], st + A_BYTES + row * A_PITCH + ks * 32 + subc * 16);
            }
            #pragma unroll
            for (int mt = 0; mt < 4; mt++)
                #pragma unroll
                for (int nt = 0; nt < 4; nt++)
                    mma16816(acc[mt][nt], Af[mt], &Bh_[nt >> 1][(nt & 1) * 2]);
        }
    }

    const int g = lane >> 2, tq = lane & 3;
    #pragma unroll
    for (int mt = 0; mt < 4; mt++) {
        #pragma unroll
        for (int nt = 0; nt < 4; nt++) {
            const int row0 = bm + wm * 64 + mt * 16 + g;
            const int col  = bn + wn * 32 + nt * 8 + tq * 2;
            #pragma unroll
            for (int h2 = 0; h2 < 2; h2++) {
                const int r = row0 + h2 * 8;
                float v0 = acc[mt][nt][h2 * 2 + 0];
                float v1 = acc[mt][nt][h2 * 2 + 1];
                if (EPI >= 1) { v0 += bias[col]; v1 += bias[col + 1]; }
                if (EPI == 2) { v0 = gelu_f(v0); v1 = gelu_f(v1); }
                if (OUT >= 1) {
                    __nv_bfloat16 h0, l0, h1, l1;
                    splitf(v0, h0, l0); splitf(v1, h1, l1);
                    *(__nv_bfloat162*)(Chi + (size_t)r * N + col) = __nv_bfloat162(h0, h1);
                    *(__nv_bfloat162*)(Clo + (size_t)r * N + col) = __nv_bfloat162(l0, l1);
                }
                if (EPI == 3) {
                    const float2 rv = *(const float2*)(R + (size_t)r * N + col);
                    v0 += rv.x; v1 += rv.y;
                }
                if (OUT != 2)
                    *(float2*)(C + (size_t)r * N + col) = make_float2(v0, v1);
            }
        }
    }
    #undef ISSUE
}

// ================= fused weight split (proven R9) =================
struct CvtArgs { const float* s[8]; };
__global__ __launch_bounds__(256) void cvt_all(
    CvtArgs a, __nv_bfloat16* __restrict__ wh, __nv_bfloat16* __restrict__ wl)
{
    int i = blockIdx.x * blockDim.x + threadIdx.x;
    int seg, off;
    if      (i <  65536) { seg = 0; off = 0; }
    else if (i < 196608) { seg = 1; off = 65536; }
    else if (i < 262144) { seg = 2; off = 196608; }
    else if (i < 327680) { seg = 3; off = 262144; }
    else if (i < 458752) { seg = 4; off = 327680; }
    else if (i < 524288) { seg = 5; off = 458752; }
    else if (i < 786432) { seg = 6; off = 524288; }
    else                 { seg = 7; off = 786432; }
    float4 v = ((const float4*)a.s[seg])[i - off];
    __nv_bfloat16 h0,l0,h1,l1,h2,l2,h3,l3;
    splitf(v.x,h0,l0); splitf(v.y,h1,l1); splitf(v.z,h2,l2); splitf(v.w,h3,l3);
    ((__nv_bfloat162*)wh)[i*2]   = __nv_bfloat162(h0,h1);
    ((__nv_bfloat162*)wh)[i*2+1] = __nv_bfloat162(h2,h3);
    ((__nv_bfloat162*)wl)[i*2]   = __nv_bfloat162(l0,l1);
    ((__nv_bfloat162*)wl)[i*2+1] = __nv_bfloat162(l2,l3);
}

// ================= group layernorm (proven R6/R9) =================
template<int MODE>
__global__ __launch_bounds__(512) void group_ln_k(
    const float* __restrict__ x, const float* __restrict__ w, const float* __restrict__ b,
    float* __restrict__ y, __nv_bfloat16* __restrict__ yh, __nv_bfloat16* __restrict__ yl)
{
    const int g = blockIdx.x;
    const float4* xg = (const float4*)(x + (size_t)g * NPG_ * DIMM);
    const float4* w4 = (const float4*)w;
    const float4* b4 = (const float4*)b;
    const int per = NPG_ * DIMM / 4;

    float s = 0.f, s2 = 0.f;
    for (int i = threadIdx.x; i < per; i += 512) {
        float4 v = xg[i];
        s  += (v.x + v.y) + (v.z + v.w);
        s2 += (v.x*v.x + v.y*v.y) + (v.z*v.z + v.w*v.w);
    }
    __shared__ float rs[16], rs2[16];
    unsigned lane = threadIdx.x & 31, wid = threadIdx.x >> 5;
    #pragma unroll
    for (int o = 16; o; o >>= 1) {
        s  += __shfl_down_sync(0xFFFFFFFFu, s,  o);
        s2 += __shfl_down_sync(0xFFFFFFFFu, s2, o);
    }
    if (lane == 0) { rs[wid] = s; rs2[wid] = s2; }
    __syncthreads();
    __shared__ float sm_mean, sm_inv;
    if (threadIdx.x == 0) {
        float ts = 0.f, ts2 = 0.f;
        #pragma unroll
        for (int i = 0; i < 16; i++) { ts += rs[i]; ts2 += rs2[i]; }
        const float cnt = (float)(NPG_ * DIMM);
        float mean = ts / cnt;
        float var  = ts2 / cnt - mean * mean;
        sm_mean = mean;
        sm_inv  = rsqrtf(var + 1e-5f);
    }
    __syncthreads();
    const float mean = sm_mean, inv = sm_inv;
    float4*          yg  = MODE ? (float4*)(y + (size_t)g * NPG_ * DIMM) : nullptr;
    __nv_bfloat162*  yh2 = (__nv_bfloat162*)(yh + (size_t)g * NPG_ * DIMM);
    __nv_bfloat162*  yl2 = (__nv_bfloat162*)(yl + (size_t)g * NPG_ * DIMM);
    for (int i = threadIdx.x; i < per; i += 512) {
        float4 v = xg[i];
        float4 wv = w4[i & 127];
        float4 bv = b4[i & 127];
        float4 r;
        r.x = (v.x - mean) * inv * wv.x + bv.x;
        r.y = (v.y - mean) * inv * wv.y + bv.y;
        r.z = (v.z - mean) * inv * wv.z + bv.z;
        r.w = (v.w - mean) * inv * wv.w + bv.w;
        if (MODE) yg[i] = r;
        __nv_bfloat16 h0,l0,h1,l1,h2,l2,h3,l3;
        splitf(r.x,h0,l0); splitf(r.y,h1,l1); splitf(r.z,h2,l2); splitf(r.w,h3,l3);
        yh2[i*2]   = __nv_bfloat162(h0,h1);
        yh2[i*2+1] = __nv_bfloat162(h2,h3);
        yl2[i*2]   = __nv_bfloat162(l0,l1);
        yl2[i*2+1] = __nv_bfloat162(l2,l3);
    }
}

// ================= SIMT attention, chunk-level softmax (32 keys/chunk) =================
// One CTA per (g,h); thread = one query row. K/V chunks double-buffered via cp.async.
// Per key: 64 FMA (QK) + 1 exp + 64 FMA (PV). o rescaled once per chunk.
#define ACH 32
#define AST_F 4096                      // floats per stage: K 32x64 + V 32x64
__global__ __launch_bounds__(256, 1) void attn_k(
    const float* __restrict__ qbuf, const float* __restrict__ kvbuf,
    __nv_bfloat16* __restrict__ oh, __nv_bfloat16* __restrict__ ol)
{
    __shared__ __align__(16) float smA[2 * AST_F];   // 32 KB
    const uint32_t sbA = smem_u32(smA);
    const int g = blockIdx.x, h = blockIdx.y;
    const int tid = threadIdx.x;
    const float* kvg = kvbuf + (size_t)g * NPG_ * 2 * DIMM;

    #define AISSUE(cc_) do {                                                      \
        const int c_ = (cc_);                                                      \
        if (c_ < 8) {                                                              \
            const uint32_t stb_ = sbA + (uint32_t)(c_ & 1) * (AST_F * 4);          \
            _Pragma("unroll")                                                      \
            for (int i2 = 0; i2 < 4; i2++) {                                       \
                int idx = tid + i2 * 256;                                          \
                int kv = idx >> 9, rem = idx & 511;                                \
                int row = rem >> 4, ch = rem & 15;                                 \
                const float* src = kvg + (size_t)(c_ * ACH + row) * (2 * DIMM)     \
                                   + (kv ? DIMM : 0) + h * DH_ + ch * 4;           \
                cp16(stb_ + kv * 8192 + row * 256 + ch * 16, src);                 \
            }                                                                      \
        }                                                                          \
        CP_COMMIT();                                                               \
    } while (0)

    float q[DH_];
    {
        const float* qr = qbuf + ((size_t)(g * NPG_ + tid)) * DIMM + h * DH_;
        #pragma unroll
        for (int d4 = 0; d4 < 16; d4++)
            *(float4*)(q + d4*4) = *(const float4*)(qr + d4*4);
    }

    AISSUE(0);
    AISSUE(1);

    float o[DH_];
    #pragma unroll
    for (int d = 0; d < DH_; d++) o[d] = 0.f;
    float m = -1e30f, l = 0.f;

    #pragma unroll 1
    for (int c = 0; c < 8; ++c) {
        CP_WAIT1();
        __syncthreads();
        const float* Kc = smA + (c & 1) * AST_F;
        const float* Vc = Kc + 2048;

        // scores for this 32-key chunk
        float s[ACH];
        float cmax = -1e30f;
        #pragma unroll
        for (int jj = 0; jj < ACH; jj++) {
            const float4* kr = (const float4*)(Kc + jj * DH_);
            float sa0 = 0.f, sa1 = 0.f, sa2 = 0.f, sa3 = 0.f;
            #pragma unroll
            for (int d4 = 0; d4 < 16; d4 += 4) {
                float4 k0 = kr[d4+0], k1 = kr[d4+1], k2 = kr[d4+2], k3 = kr[d4+3];
                sa0 += q[(d4+0)*4+0]*k0.x + q[(d4+0)*4+1]*k0.y + q[(d4+0)*4+2]*k0.z + q[(d4+0)*4+3]*k0.w;
                sa1 += q[(d4+1)*4+0]*k1.x + q[(d4+1)*4+1]*k1.y + q[(d4+1)*4+2]*k1.z + q[(d4+1)*4+3]*k1.w;
                sa2 += q[(d4+2)*4+0]*k2.x + q[(d4+2)*4+1]*k2.y + q[(d4+2)*4+2]*k2.z + q[(d4+2)*4+3]*k2.w;
                sa3 += q[(d4+3)*4+0]*k3.x + q[(d4+3)*4+1]*k3.y + q[(d4+3)*4+2]*k3.z + q[(d4+3)*4+3]*k3.w;
            }
            s[jj] = ((sa0 + sa1) + (sa2 + sa3)) * 0.125f;
            cmax = fmaxf(cmax, s[jj]);
        }

        // one rescale per chunk
        const float nm   = fmaxf(m, cmax);
        const float corr = __expf(m - nm);
        m = nm;
        l *= corr;
        #pragma unroll
        for (int d = 0; d < DH_; d++) o[d] *= corr;

        // accumulate (1 exp/key, 1 FMA/element)
        #pragma unroll
        for (int jj = 0; jj < ACH; jj++) {
            const float p = __expf(s[jj] - nm);
            l += p;
            const float4* vr = (const float4*)(Vc + jj * DH_);
            #pragma unroll
            for (int d4 = 0; d4 < 16; d4++) {
                float4 v4 = vr[d4];
                o[d4*4+0] += p * v4.x;
                o[d4*4+1] += p * v4.y;
                o[d4*4+2] += p * v4.z;
                o[d4*4+3] += p * v4.w;
            }
        }

        __syncthreads();
        AISSUE(c + 2);
    }

    const float invl = 1.f / l;
    const size_t rb = ((size_t)(g * NPG_ + tid)) * DIMM + h * DH_;
    __nv_bfloat162* oh2 = (__nv_bfloat162*)(oh + rb);
    __nv_bfloat162* ol2 = (__nv_bfloat162*)(ol + rb);
    #pragma unroll
    for (int d2 = 0; d2 < 32; d2++) {
        float v0 = o[d2*2+0] * invl, v1 = o[d2*2+1] * invl;
        __nv_bfloat16 h0,l0,h1,l1;
        splitf(v0,h0,l0); splitf(v1,h1,l1);
        oh2[d2] = __nv_bfloat162(h0,h1);
        ol2[d2] = __nv_bfloat162(l0,l1);
    }
    #undef AISSUE
}

// ================= launch (identical plumbing to passing R9) =================
extern "C" void kernel_launch(void* const* d_in, const int* in_sizes, int n_in,
                              void* d_out, int out_size)
{
    (void)in_sizes; (void)n_in; (void)out_size;
    const float* x        = (const float*)d_in[0];
    const float* queries  = (const float*)d_in[1];
    const float* ln_seq_w = (const float*)d_in[3];
    const float* ln_seq_b = (const float*)d_in[4];
    const float* ln_q_w   = (const float*)d_in[5];
    const float* ln_q_b   = (const float*)d_in[6];
    const float* a1_Wq    = (const float*)d_in[7];
    const float* a1_Wkv   = (const float*)d_in[8];
    const float* a1_Wo    = (const float*)d_in[9];
    const float* a1_bo    = (const float*)d_in[10];
    const float* a2_Wq    = (const float*)d_in[11];
    const float* a2_Wkv   = (const float*)d_in[12];
    const float* a2_Wo    = (const float*)d_in[13];
    const float* a2_bo    = (const float*)d_in[14];
    const float* ff_ln_w  = (const float*)d_in[15];
    const float* ff_ln_b  = (const float*)d_in[16];
    const float* ff_W1    = (const float*)d_in[17];
    const float* ff_b1    = (const float*)d_in[18];
    const float* ff_W2    = (const float*)d_in[19];
    const float* ff_b2    = (const float*)d_in[20];

    float* out_x = (float*)d_out;
    float* out_q = out_x + SBUF;

    float* pool;  __nv_bfloat16* act;  __nv_bfloat16* wt;
    cudaGetSymbolAddress((void**)&pool, g_pool);
    cudaGetSymbolAddress((void**)&act,  g_act);
    cudaGetSymbolAddress((void**)&wt,   g_wt);

    float* p_q   = pool;                  // dead after attn2 -> x2
    float* p_kv  = pool + 1 * SBUF;       // dead after attn2 -> xn2
    float* p_x2  = pool;
    float* p_xn2 = pool + 1 * SBUF;

    __nv_bfloat16* xn_h = act + 0 * SBUF; __nv_bfloat16* xn_l = act + 1 * SBUF;
    __nv_bfloat16* qn_h = act + 2 * SBUF; __nv_bfloat16* qn_l = act + 3 * SBUF;
    __nv_bfloat16* o_h  = act + 2 * SBUF; __nv_bfloat16* o_l  = act + 3 * SBUF;  // overlay qn (dead)
    __nv_bfloat16* in_h = act + 4 * SBUF; __nv_bfloat16* in_l = act + 5 * SBUF;
    __nv_bfloat16* x2_h = act + 0 * SBUF; __nv_bfloat16* x2_l = act + 1 * SBUF;  // overlay xn (dead)
    __nv_bfloat16* h_h  = act + 2 * SBUF; __nv_bfloat16* h_l  = act + 4 * SBUF;  // half-token h pair

    const size_t OWQ1 = 0,        OWKV1 = 262144,  OWO1 = 786432;
    const size_t OWQ2 = 1048576,  OWKV2 = 1310720, OWO2 = 1835008;
    const size_t OW1  = 2097152,  OW2   = 3145728;
    __nv_bfloat16* wh = wt;  __nv_bfloat16* wl = wt + WTOT;

    cudaFuncSetAttribute(gemm_bf<0,0>, cudaFuncAttributeMaxDynamicSharedMemorySize, GEMM_SMEM);
    cudaFuncSetAttribute(gemm_bf<3,1>, cudaFuncAttributeMaxDynamicSharedMemorySize, GEMM_SMEM);
    cudaFuncSetAttribute(gemm_bf<2,2>, cudaFuncAttributeMaxDynamicSharedMemorySize, GEMM_SMEM);
    cudaFuncSetAttribute(gemm_bf<3,0>, cudaFuncAttributeMaxDynamicSharedMemorySize, GEMM_SMEM);

    CvtArgs ca;
    ca.s[0]=a1_Wq; ca.s[1]=a1_Wkv; ca.s[2]=a1_Wo; ca.s[3]=a2_Wq;
    ca.s[4]=a2_Wkv; ca.s[5]=a2_Wo; ca.s[6]=ff_W1; ca.s[7]=ff_W2;
    cvt_all<<<4096, 256>>>(ca, wh, wl);

    const dim3 gN512 (4,  NTOK/BM);      // (4, 256)
    const dim3 gN1024(8,  NTOK/BM);      // (8, 256)
    const dim3 attng(G_, HEADS_);

    group_ln_k<0><<<G_, 512>>>(x,       ln_seq_w, ln_seq_b, nullptr, xn_h, xn_l);
    group_ln_k<0><<<G_, 512>>>(queries, ln_q_w,   ln_q_b,   nullptr, qn_h, qn_l);

    // Attention 1: induced = attn(ln(queries), ln(x))
    gemm_bf<0,0><<<gN512,  256, GEMM_SMEM>>>(qn_h, qn_l, wh+OWQ1,  wl+OWQ1,  nullptr, nullptr,
                                             p_q,  nullptr, nullptr, NTOK, DIMM,   DIMM);
    gemm_bf<0,0><<<gN1024, 256, GEMM_SMEM>>>(xn_h, xn_l, wh+OWKV1, wl+OWKV1, nullptr, nullptr,
                                             p_kv, nullptr, nullptr, NTOK, 2*DIMM, DIMM);
    attn_k<<<attng, 256>>>(p_q, p_kv, o_h, o_l);
    // induced pair -> in_h/in_l ; q2 = induced + queries -> out_q (fused)
    gemm_bf<3,1><<<gN512,  256, GEMM_SMEM>>>(o_h, o_l, wh+OWO1, wl+OWO1, a1_bo, queries,
                                             out_q, in_h, in_l, NTOK, DIMM, DIMM);

    // Attention 2: out = attn(ln(x), induced); x2 = out + x (fused)
    gemm_bf<0,0><<<gN512,  256, GEMM_SMEM>>>(xn_h, xn_l, wh+OWQ2,  wl+OWQ2,  nullptr, nullptr,
                                             p_q,  nullptr, nullptr, NTOK, DIMM,   DIMM);
    gemm_bf<0,0><<<gN1024, 256, GEMM_SMEM>>>(in_h, in_l, wh+OWKV2, wl+OWKV2, nullptr, nullptr,
                                             p_kv, nullptr, nullptr, NTOK, 2*DIMM, DIMM);
    attn_k<<<attng, 256>>>(p_q, p_kv, o_h, o_l);
    gemm_bf<3,0><<<gN512,  256, GEMM_SMEM>>>(o_h, o_l, wh+OWO2, wl+OWO2, a2_bo, x,
                                             p_x2, nullptr, nullptr, NTOK, DIMM, DIMM);

    // FF block: LN, then two M-halves through the 4*SBUF-sized h pair buffer
    group_ln_k<1><<<G_, 512>>>(p_x2, ff_ln_w, ff_ln_b, p_xn2, x2_h, x2_l);

    const int MH = NTOK / 2;                       // 16384 rows per half
    const dim3 gFF1(4 * DIMM / BN, MH / BM);       // (16, 128)
    const dim3 gFF2(DIMM / BN,     MH / BM);       // (4, 128)
    for (int half = 0; half < 2; half++) {
        const size_t aoff = (size_t)half * MH * DIMM;
        gemm_bf<2,2><<<gFF1, 256, GEMM_SMEM>>>(x2_h + aoff, x2_l + aoff, wh+OW1, wl+OW1,
                                               ff_b1, nullptr,
                                               nullptr, h_h, h_l, MH, 4*DIMM, DIMM);
        gemm_bf<3,0><<<gFF2, 256, GEMM_SMEM>>>(h_h, h_l, wh+OW2, wl+OW2,
                                               ff_b2, p_xn2 + aoff,
                                               out_x + aoff, nullptr, nullptr,
                                               MH, DIMM, 4*DIMM);
    }
}

// round 15
// speedup vs baseline: 1.4124x; 1.2889x over previous
#include <cuda_runtime.h>
#include <cuda_bf16.h>
#include <math.h>
#include <stdint.h>

#define G_      128
#define NPG_    256
#define DIMM    512
#define HEADS_  8
#define DH_     64
#define NTOK    (G_*NPG_)                  // 32768
#define SBUF    ((size_t)NTOK * DIMM)      // 16,777,216 elems

// ---------------- scratch (identical decls to passing rounds: ~400 MB) ----------------
__device__ float g_pool[3 * SBUF];
__device__ __nv_bfloat16 g_act[6 * SBUF];
#define WTOT 4194304
__device__ __nv_bfloat16 g_wt[2 * WTOT];

// ================= helpers =================
__device__ __forceinline__ uint32_t smem_u32(const void* p) {
    uint32_t a;
    asm("{ .reg .u64 t; cvta.to.shared.u64 t, %1; cvt.u32.u64 %0, t; }" : "=r"(a) : "l"(p));
    return a;
}
__device__ __forceinline__ void cp16(uint32_t dst, const void* src) {
    asm volatile("cp.async.cg.shared.global [%0], [%1], 16;" :: "r"(dst), "l"(src));
}
#define CP_COMMIT() asm volatile("cp.async.commit_group;")
#define CP_WAIT1()  asm volatile("cp.async.wait_group 1;")

__device__ __forceinline__ void ldsm4(uint32_t* r, uint32_t addr) {
    asm volatile("ldmatrix.sync.aligned.m8n8.x4.shared.b16 {%0,%1,%2,%3}, [%4];"
        : "=r"(r[0]), "=r"(r[1]), "=r"(r[2]), "=r"(r[3]) : "r"(addr));
}
__device__ __forceinline__ void ldsm4t(uint32_t* r, uint32_t addr) {
    asm volatile("ldmatrix.sync.aligned.m8n8.x4.trans.shared.b16 {%0,%1,%2,%3}, [%4];"
        : "=r"(r[0]), "=r"(r[1]), "=r"(r[2]), "=r"(r[3]) : "r"(addr));
}
__device__ __forceinline__ void mma16816(float* d, const uint32_t* a, const uint32_t* b) {
    asm volatile("mma.sync.aligned.m16n8k16.row.col.f32.bf16.bf16.f32 "
        "{%0,%1,%2,%3}, {%4,%5,%6,%7}, {%8,%9}, {%0,%1,%2,%3};"
        : "+f"(d[0]), "+f"(d[1]), "+f"(d[2]), "+f"(d[3])
        : "r"(a[0]), "r"(a[1]), "r"(a[2]), "r"(a[3]), "r"(b[0]), "r"(b[1]));
}
__device__ __forceinline__ void splitf(float x, __nv_bfloat16& h, __nv_bfloat16& l) {
    h = __float2bfloat16_rn(x);
    l = __float2bfloat16_rn(x - __bfloat162float(h));
}
__device__ __forceinline__ uint32_t packbf(float a, float b) {
    __nv_bfloat162 t(__float2bfloat16_rn(a), __float2bfloat16_rn(b));
    return *(uint32_t*)&t;
}
__device__ __forceinline__ float bflo(uint32_t p, int i) {
    __nv_bfloat162 t = *(__nv_bfloat162*)&p;
    return i ? __bfloat162float(t.y) : __bfloat162float(t.x);
}
__device__ __forceinline__ float gelu_f(float v) {
    return 0.5f * v * (1.f + erff(v * 0.70710678118654752f));
}

// ================= bf16x3 tensor-core GEMM (proven) =================
#define BM 128
#define BN 128
#define BK 32
#define A_PITCH 80
#define B_PITCH 272
#define A_BYTES (BM*A_PITCH)
#define B_BYTES (BK*B_PITCH)
#define STAGE_B (2*A_BYTES + 2*B_BYTES)
#define NSTG 3
#define GEMM_SMEM (NSTG*STAGE_B)

template<int EPI, int OUT>
__global__ __launch_bounds__(256, 2) void gemm_bf(
    const __nv_bfloat16* __restrict__ Ahi, const __nv_bfloat16* __restrict__ Alo,
    const __nv_bfloat16* __restrict__ Bhi, const __nv_bfloat16* __restrict__ Blo,
    const float* __restrict__ bias, const float* __restrict__ R,
    float* __restrict__ C, __nv_bfloat16* __restrict__ Chi, __nv_bfloat16* __restrict__ Clo,
    int M, int N, int K)
{
    extern __shared__ __align__(16) char sm[];
    const uint32_t sb = smem_u32(sm);
    const int tid = threadIdx.x;
    const int lane = tid & 31, warp = tid >> 5;
    const int wm = warp & 1, wn = warp >> 1;
    const int bm = blockIdx.y * BM, bn = blockIdx.x * BN;
    const int CCH = K / BK;

    float acc[4][4][4];
    #pragma unroll
    for (int a = 0; a < 4; a++)
        #pragma unroll
        for (int b = 0; b < 4; b++)
            #pragma unroll
            for (int k = 0; k < 4; k++) acc[a][b][k] = 0.f;

    #define ISSUE(cc_)  do {                                                       \
        const int c_ = (cc_);                                                      \
        if (c_ < CCH) {                                                            \
            const uint32_t st_ = sb + (c_ % NSTG) * STAGE_B;                       \
            const int k0_ = c_ * BK;                                               \
            _Pragma("unroll")                                                      \
            for (int i = 0; i < 4; i++) {                                          \
                int idx = tid + i * 256;                                           \
                int sel = idx >> 9, rem = idx & 511;                               \
                int row = rem >> 2, ch = rem & 3;                                  \
                const __nv_bfloat16* s = (sel ? Alo : Ahi)                         \
                    + (size_t)(bm + row) * K + k0_ + ch * 8;                       \
                cp16(st_ + sel * A_BYTES + row * A_PITCH + ch * 16, s);            \
            }                                                                      \
            _Pragma("unroll")                                                      \
            for (int i = 0; i < 4; i++) {                                          \
                int idx = tid + i * 256;                                           \
                int sel = idx >> 9, rem = idx & 511;                               \
                int kr = rem >> 4, ch = rem & 15;                                  \
                const __nv_bfloat16* s = (sel ? Blo : Bhi)                         \
                    + (size_t)(k0_ + kr) * N + bn + ch * 8;                        \
                cp16(st_ + 2 * A_BYTES + sel * B_BYTES + kr * B_PITCH + ch * 16, s);\
            }                                                                      \
        }                                                                          \
        CP_COMMIT();                                                               \
    } while (0)

    ISSUE(0);
    ISSUE(1);

    const int r8 = lane & 7, sub = lane >> 3;
    const int subr = (sub & 1) * 8, subc = sub >> 1;

    for (int c = 0; c < CCH; ++c) {
        CP_WAIT1();
        __syncthreads();
        ISSUE(c + 2);
        const uint32_t st = sb + (c % NSTG) * STAGE_B;
        #pragma unroll
        for (int ks = 0; ks < 2; ++ks) {
            uint32_t Af[4][4], Bh_[2][4], Bl_[2][4];
            #pragma unroll
            for (int mt = 0; mt < 4; mt++) {
                int row = wm * 64 + mt * 16 + r8 + subr;
                ldsm4(Af[mt], st + row * A_PITCH + ks * 32 + subc * 16);
            }
            #pragma unroll
            for (int p = 0; p < 2; p++) {
                int kr = ks * 16 + r8 + subr;
                int nc = wn * 32 + p * 16 + subc * 8;
                ldsm4t(Bh_[p], st + 2 * A_BYTES + kr * B_PITCH + nc * 2);
            }
            #pragma unroll
            for (int mt = 0; mt < 4; mt++)
                #pragma unroll
                for (int nt = 0; nt < 4; nt++)
                    mma16816(acc[mt][nt], Af[mt], &Bh_[nt >> 1][(nt & 1) * 2]);
            #pragma unroll
            for (int p = 0; p < 2; p++) {
                int kr = ks * 16 + r8 + subr;
                int nc = wn * 32 + p * 16 + subc * 8;
                ldsm4t(Bl_[p], st + 2 * A_BYTES + B_BYTES + kr * B_PITCH + nc * 2);
            }
            #pragma unroll
            for (int mt = 0; mt < 4; mt++)
                #pragma unroll
                for (int nt = 0; nt < 4; nt++)
                    mma16816(acc[mt][nt], Af[mt], &Bl_[nt >> 1][(nt & 1) * 2]);
            #pragma unroll
            for (int mt = 0; mt < 4; mt++) {
                int row = wm * 64 + mt * 16 + r8 + subr;
                ldsm4(Af[mt], st + A_BYTES + row * A_PITCH + ks * 32 + subc * 16);
            }
            #pragma unroll
            for (int mt = 0; mt < 4; mt++)
                #pragma unroll
                for (int nt = 0; nt < 4; nt++)
                    mma16816(acc[mt][nt], Af[mt], &Bh_[nt >> 1][(nt & 1) * 2]);
        }
    }

    const int g = lane >> 2, tq = lane & 3;
    #pragma unroll
    for (int mt = 0; mt < 4; mt++) {
        #pragma unroll
        for (int nt = 0; nt < 4; nt++) {
            const int row0 = bm + wm * 64 + mt * 16 + g;
            const int col  = bn + wn * 32 + nt * 8 + tq * 2;
            #pragma unroll
            for (int h2 = 0; h2 < 2; h2++) {
                const int r = row0 + h2 * 8;
                float v0 = acc[mt][nt][h2 * 2 + 0];
                float v1 = acc[mt][nt][h2 * 2 + 1];
                if (EPI >= 1) { v0 += bias[col]; v1 += bias[col + 1]; }
                if (EPI == 2) { v0 = gelu_f(v0); v1 = gelu_f(v1); }
                if (OUT >= 1) {
                    __nv_bfloat16 h0, l0, h1, l1;
                    splitf(v0, h0, l0); splitf(v1, h1, l1);
                    *(__nv_bfloat162*)(Chi + (size_t)r * N + col) = __nv_bfloat162(h0, h1);
                    *(__nv_bfloat162*)(Clo + (size_t)r * N + col) = __nv_bfloat162(l0, l1);
                }
                if (EPI == 3) {
                    const float2 rv = *(const float2*)(R + (size_t)r * N + col);
                    v0 += rv.x; v1 += rv.y;
                }
                if (OUT != 2)
                    *(float2*)(C + (size_t)r * N + col) = make_float2(v0, v1);
            }
        }
    }
    #undef ISSUE
}

// ================= fused weight split =================
struct CvtArgs { const float* s[8]; };
__global__ __launch_bounds__(256) void cvt_all(
    CvtArgs a, __nv_bfloat16* __restrict__ wh, __nv_bfloat16* __restrict__ wl)
{
    int i = blockIdx.x * blockDim.x + threadIdx.x;
    int seg, off;
    if      (i <  65536) { seg = 0; off = 0; }
    else if (i < 196608) { seg = 1; off = 65536; }
    else if (i < 262144) { seg = 2; off = 196608; }
    else if (i < 327680) { seg = 3; off = 262144; }
    else if (i < 458752) { seg = 4; off = 327680; }
    else if (i < 524288) { seg = 5; off = 458752; }
    else if (i < 786432) { seg = 6; off = 524288; }
    else                 { seg = 7; off = 786432; }
    float4 v = ((const float4*)a.s[seg])[i - off];
    __nv_bfloat16 h0,l0,h1,l1,h2,l2,h3,l3;
    splitf(v.x,h0,l0); splitf(v.y,h1,l1); splitf(v.z,h2,l2); splitf(v.w,h3,l3);
    ((__nv_bfloat162*)wh)[i*2]   = __nv_bfloat162(h0,h1);
    ((__nv_bfloat162*)wh)[i*2+1] = __nv_bfloat162(h2,h3);
    ((__nv_bfloat162*)wl)[i*2]   = __nv_bfloat162(l0,l1);
    ((__nv_bfloat162*)wl)[i*2+1] = __nv_bfloat162(l2,l3);
}

// ================= group layernorm (proven) =================
template<int MODE>
__global__ __launch_bounds__(512) void group_ln_k(
    const float* __restrict__ x, const float* __restrict__ w, const float* __restrict__ b,
    float* __restrict__ y, __nv_bfloat16* __restrict__ yh, __nv_bfloat16* __restrict__ yl)
{
    const int g = blockIdx.x;
    const float4* xg = (const float4*)(x + (size_t)g * NPG_ * DIMM);
    const float4* w4 = (const float4*)w;
    const float4* b4 = (const float4*)b;
    const int per = NPG_ * DIMM / 4;

    float s = 0.f, s2 = 0.f;
    for (int i = threadIdx.x; i < per; i += 512) {
        float4 v = xg[i];
        s  += (v.x + v.y) + (v.z + v.w);
        s2 += (v.x*v.x + v.y*v.y) + (v.z*v.z + v.w*v.w);
    }
    __shared__ float rs[16], rs2[16];
    unsigned lane = threadIdx.x & 31, wid = threadIdx.x >> 5;
    #pragma unroll
    for (int o = 16; o; o >>= 1) {
        s  += __shfl_down_sync(0xFFFFFFFFu, s,  o);
        s2 += __shfl_down_sync(0xFFFFFFFFu, s2, o);
    }
    if (lane == 0) { rs[wid] = s; rs2[wid] = s2; }
    __syncthreads();
    __shared__ float sm_mean, sm_inv;
    if (threadIdx.x == 0) {
        float ts = 0.f, ts2 = 0.f;
        #pragma unroll
        for (int i = 0; i < 16; i++) { ts += rs[i]; ts2 += rs2[i]; }
        const float cnt = (float)(NPG_ * DIMM);
        float mean = ts / cnt;
        float var  = ts2 / cnt - mean * mean;
        sm_mean = mean;
        sm_inv  = rsqrtf(var + 1e-5f);
    }
    __syncthreads();
    const float mean = sm_mean, inv = sm_inv;
    float4*          yg  = MODE ? (float4*)(y + (size_t)g * NPG_ * DIMM) : nullptr;
    __nv_bfloat162*  yh2 = (__nv_bfloat162*)(yh + (size_t)g * NPG_ * DIMM);
    __nv_bfloat162*  yl2 = (__nv_bfloat162*)(yl + (size_t)g * NPG_ * DIMM);
    for (int i = threadIdx.x; i < per; i += 512) {
        float4 v = xg[i];
        float4 wv = w4[i & 127];
        float4 bv = b4[i & 127];
        float4 r;
        r.x = (v.x - mean) * inv * wv.x + bv.x;
        r.y = (v.y - mean) * inv * wv.y + bv.y;
        r.z = (v.z - mean) * inv * wv.z + bv.z;
        r.w = (v.w - mean) * inv * wv.w + bv.w;
        if (MODE) yg[i] = r;
        __nv_bfloat16 h0,l0,h1,l1,h2,l2,h3,l3;
        splitf(r.x,h0,l0); splitf(r.y,h1,l1); splitf(r.z,h2,l2); splitf(r.w,h3,l3);
        yh2[i*2]   = __nv_bfloat162(h0,h1);
        yh2[i*2+1] = __nv_bfloat162(h2,h3);
        yl2[i*2]   = __nv_bfloat162(l0,l1);
        yl2[i*2+1] = __nv_bfloat162(l2,l3);
    }
}

// ================= flash-chunked MMA attention =================
// Grid (G_, HEADS_, 2). 256 thr / 8 warps; warp owns 16 q rows (CTA: 128).
// Online softmax over 4 key-chunks of 64; K/V double-buffered cp.async.
#define FAP 144
#define FQ_BYTES (128*FAP)
#define SFQH 0
#define SFQL (SFQH + FQ_BYTES)
#define FCH_BYTES (64*FAP)
#define FSTG (4*FCH_BYTES)
#define SFK  (SFQL + FQ_BYTES)
#define FA_SMEM (SFK + 2*FSTG)        // 110592

__global__ __launch_bounds__(256, 1) void attn_fa(
    const __nv_bfloat16* __restrict__ qh, const __nv_bfloat16* __restrict__ ql,
    const __nv_bfloat16* __restrict__ kvh, const __nv_bfloat16* __restrict__ kvl,
    __nv_bfloat16* __restrict__ oh, __nv_bfloat16* __restrict__ ol)
{
    extern __shared__ __align__(16) char sm[];
    const uint32_t sb = smem_u32(sm);
    const int tid = threadIdx.x;
    const int lane = tid & 31, w = tid >> 5;
    const int g = blockIdx.x, h = blockIdx.y, mh = blockIdx.z;
    const int tq0 = g * NPG_ + mh * 128;
    const int tk0 = g * NPG_;

    #define FA_ISSUE(cc_) do {                                                     \
        const int c_ = (cc_);                                                      \
        const uint32_t stb_ = sb + SFK + (c_ & 1) * FSTG;                          \
        _Pragma("unroll")                                                          \
        for (int i = 0; i < 8; i++) {                                              \
            int idx = tid + i * 256;                                               \
            int buf = idx >> 9, rem = idx & 511;                                   \
            int row = rem >> 3, ch = rem & 7;                                      \
            const __nv_bfloat16* base = (buf & 1) ? kvl : kvh;                     \
            size_t off = (size_t)(tk0 + c_ * 64 + row) * (2 * DIMM)                \
                         + ((buf >> 1) ? DIMM : 0) + h * DH_ + ch * 8;             \
            cp16(stb_ + buf * FCH_BYTES + row * FAP + ch * 16, base + off);        \
        }                                                                          \
    } while (0)

    #pragma unroll
    for (int i = 0; i < 8; i++) {
        int idx = tid + i * 256;
        int buf = idx >> 10, rem = idx & 1023;
        int row = rem >> 3, ch = rem & 7;
        const __nv_bfloat16* base = buf ? ql : qh;
        cp16(sb + (buf ? SFQL : SFQH) + row * FAP + ch * 16,
             base + (size_t)(tq0 + row) * DIMM + h * DH_ + ch * 8);
    }
    FA_ISSUE(0);
    CP_COMMIT();
    FA_ISSUE(1);
    CP_COMMIT();

    const int l7 = lane & 7;
    const int b3 = (lane >> 3) & 1;
    const int b4 = (lane >> 4) & 1;

    CP_WAIT1();
    __syncthreads();

    uint32_t Qh[4][4], Ql[4][4];
    {
        const uint32_t qrow = w * 16 + l7 + 8 * b3;
        #pragma unroll
        for (int kc = 0; kc < 4; kc++) {
            ldsm4(Qh[kc], sb + SFQH + qrow * FAP + kc * 32 + b4 * 16);
            ldsm4(Ql[kc], sb + SFQL + qrow * FAP + kc * 32 + b4 * 16);
        }
    }

    float O[8][4];
    #pragma unroll
    for (int nd = 0; nd < 8; nd++)
        #pragma unroll
        for (int k = 0; k < 4; k++) O[nd][k] = 0.f;
    float m0 = -1e30f, m1 = -1e30f, l0 = 0.f, l1 = 0.f;
    const float sc8 = 0.125f;

    #pragma unroll 1
    for (int c = 0; c < 4; ++c) {
        if (c > 0) { CP_WAIT1(); __syncthreads(); }
        const uint32_t stg = sb + SFK + (c & 1) * FSTG;

        float S[8][4];
        #pragma unroll
        for (int nt = 0; nt < 8; nt++)
            #pragma unroll
            for (int k = 0; k < 4; k++) S[nt][k] = 0.f;
        #pragma unroll
        for (int kc = 0; kc < 4; kc++) {
            #pragma unroll
            for (int nt2 = 0; nt2 < 4; nt2++) {
                uint32_t kh[4], kl[4];
                const uint32_t krow = nt2 * 16 + l7 + 8 * b4;
                ldsm4(kh, stg + 0 * FCH_BYTES + krow * FAP + kc * 32 + b3 * 16);
                ldsm4(kl, stg + 1 * FCH_BYTES + krow * FAP + kc * 32 + b3 * 16);
                mma16816(S[2*nt2],   Qh[kc], kh);
                mma16816(S[2*nt2+1], Qh[kc], kh + 2);
                mma16816(S[2*nt2],   Ql[kc], kh);
                mma16816(S[2*nt2+1], Ql[kc], kh + 2);
                mma16816(S[2*nt2],   Qh[kc], kl);
                mma16816(S[2*nt2+1], Qh[kc], kl + 2);
            }
        }

        float cmx0 = -1e30f, cmx1 = -1e30f;
        #pragma unroll
        for (int nt = 0; nt < 8; nt++) {
            cmx0 = fmaxf(cmx0, fmaxf(S[nt][0], S[nt][1]));
            cmx1 = fmaxf(cmx1, fmaxf(S[nt][2], S[nt][3]));
        }
        cmx0 = fmaxf(cmx0, __shfl_xor_sync(0xFFFFFFFFu, cmx0, 1));
        cmx0 = fmaxf(cmx0, __shfl_xor_sync(0xFFFFFFFFu, cmx0, 2));
        cmx1 = fmaxf(cmx1, __shfl_xor_sync(0xFFFFFFFFu, cmx1, 1));
        cmx1 = fmaxf(cmx1, __shfl_xor_sync(0xFFFFFFFFu, cmx1, 2));
        const float nm0 = fmaxf(m0, cmx0);
        const float nm1 = fmaxf(m1, cmx1);
        const float cr0 = __expf(sc8 * (m0 - nm0));
        const float cr1 = __expf(sc8 * (m1 - nm1));
        m0 = nm0; m1 = nm1;
        float cs0 = 0.f, cs1 = 0.f;
        #pragma unroll
        for (int nt = 0; nt < 8; nt++) {
            float p0 = __expf(sc8 * (S[nt][0] - nm0));
            float p1 = __expf(sc8 * (S[nt][1] - nm0));
            float p2 = __expf(sc8 * (S[nt][2] - nm1));
            float p3 = __expf(sc8 * (S[nt][3] - nm1));
            S[nt][0] = p0; S[nt][1] = p1; S[nt][2] = p2; S[nt][3] = p3;
            cs0 += p0 + p1; cs1 += p2 + p3;
        }
        cs0 += __shfl_xor_sync(0xFFFFFFFFu, cs0, 1);
        cs0 += __shfl_xor_sync(0xFFFFFFFFu, cs0, 2);
        cs1 += __shfl_xor_sync(0xFFFFFFFFu, cs1, 1);
        cs1 += __shfl_xor_sync(0xFFFFFFFFu, cs1, 2);
        l0 = l0 * cr0 + cs0;
        l1 = l1 * cr1 + cs1;
        #pragma unroll
        for (int nd = 0; nd < 8; nd++) {
            O[nd][0] *= cr0; O[nd][1] *= cr0;
            O[nd][2] *= cr1; O[nd][3] *= cr1;
        }

        #pragma unroll
        for (int j = 0; j < 4; j++) {
            uint32_t pah[4], pal[4];
            {
                const float* t0 = S[2*j];
                const float* t1 = S[2*j+1];
                pah[0] = packbf(t0[0], t0[1]);
                pah[1] = packbf(t0[2], t0[3]);
                pah[2] = packbf(t1[0], t1[1]);
                pah[3] = packbf(t1[2], t1[3]);
                pal[0] = packbf(t0[0] - bflo(pah[0],0), t0[1] - bflo(pah[0],1));
                pal[1] = packbf(t0[2] - bflo(pah[1],0), t0[3] - bflo(pah[1],1));
                pal[2] = packbf(t1[0] - bflo(pah[2],0), t1[1] - bflo(pah[2],1));
                pal[3] = packbf(t1[2] - bflo(pah[3],0), t1[3] - bflo(pah[3],1));
            }
            const uint32_t vrow = j * 16 + l7 + 8 * b3;
            #pragma unroll
            for (int nd2 = 0; nd2 < 4; nd2++) {
                uint32_t vh[4], vl[4];
                ldsm4t(vh, stg + 2 * FCH_BYTES + vrow * FAP + (nd2 * 16 + b4 * 8) * 2);
                ldsm4t(vl, stg + 3 * FCH_BYTES + vrow * FAP + (nd2 * 16 + b4 * 8) * 2);
                mma16816(O[2*nd2],   pah, vh);
                mma16816(O[2*nd2+1], pah, vh + 2);
                mma16816(O[2*nd2],   pal, vh);
                mma16816(O[2*nd2+1], pal, vh + 2);
                mma16816(O[2*nd2],   pah, vl);
                mma16816(O[2*nd2+1], pah, vl + 2);
            }
        }

        __syncthreads();
        if (c + 2 < 4) FA_ISSUE(c + 2);
        CP_COMMIT();
    }

    const float inv0 = 1.f / l0, inv1 = 1.f / l1;
    const int row_lo = tq0 + w * 16 + (lane >> 2);
    #pragma unroll
    for (int nd = 0; nd < 8; nd++) {
        const int col = h * DH_ + nd * 8 + (lane & 3) * 2;
        float v0 = O[nd][0] * inv0, v1 = O[nd][1] * inv0;
        float v2 = O[nd][2] * inv1, v3 = O[nd][3] * inv1;
        __nv_bfloat16 h0,lo0,h1,lo1;
        splitf(v0,h0,lo0); splitf(v1,h1,lo1);
        *(__nv_bfloat162*)(oh + (size_t)row_lo * DIMM + col) = __nv_bfloat162(h0,h1);
        *(__nv_bfloat162*)(ol + (size_t)row_lo * DIMM + col) = __nv_bfloat162(lo0,lo1);
        splitf(v2,h0,lo0); splitf(v3,h1,lo1);
        *(__nv_bfloat162*)(oh + (size_t)(row_lo + 8) * DIMM + col) = __nv_bfloat162(h0,h1);
        *(__nv_bfloat162*)(ol + (size_t)(row_lo + 8) * DIMM + col) = __nv_bfloat162(lo0,lo1);
    }
    #undef FA_ISSUE
}

// ================= launch =================
extern "C" void kernel_launch(void* const* d_in, const int* in_sizes, int n_in,
                              void* d_out, int out_size)
{
    (void)in_sizes; (void)n_in; (void)out_size;
    const float* x        = (const float*)d_in[0];
    const float* queries  = (const float*)d_in[1];
    const float* ln_seq_w = (const float*)d_in[3];
    const float* ln_seq_b = (const float*)d_in[4];
    const float* ln_q_w   = (const float*)d_in[5];
    const float* ln_q_b   = (const float*)d_in[6];
    const float* a1_Wq    = (const float*)d_in[7];
    const float* a1_Wkv   = (const float*)d_in[8];
    const float* a1_Wo    = (const float*)d_in[9];
    const float* a1_bo    = (const float*)d_in[10];
    const float* a2_Wq    = (const float*)d_in[11];
    const float* a2_Wkv   = (const float*)d_in[12];
    const float* a2_Wo    = (const float*)d_in[13];
    const float* a2_bo    = (const float*)d_in[14];
    const float* ff_ln_w  = (const float*)d_in[15];
    const float* ff_ln_b  = (const float*)d_in[16];
    const float* ff_W1    = (const float*)d_in[17];
    const float* ff_b1    = (const float*)d_in[18];
    const float* ff_W2    = (const float*)d_in[19];
    const float* ff_b2    = (const float*)d_in[20];

    float* out_x = (float*)d_out;
    float* out_q = out_x + SBUF;

    float* pool;  __nv_bfloat16* act;  __nv_bfloat16* wt;
    cudaGetSymbolAddress((void**)&pool, g_pool);
    cudaGetSymbolAddress((void**)&act,  g_act);
    cudaGetSymbolAddress((void**)&wt,   g_wt);

    // g_pool reinterpreted as 6 bf16-units: q pair [0,2), kv pair [2,6)
    __nv_bfloat16* P = (__nv_bfloat16*)pool;
    __nv_bfloat16* q_h  = P + 0 * SBUF; __nv_bfloat16* q_l  = P + 1 * SBUF;
    __nv_bfloat16* kv_h = P + 2 * SBUF; __nv_bfloat16* kv_l = P + 4 * SBUF;
    float* p_x2  = pool;                  // overlay q/kv (dead after attn2)
    float* p_xn2 = pool + 1 * SBUF;

    __nv_bfloat16* xn_h = act + 0 * SBUF; __nv_bfloat16* xn_l = act + 1 * SBUF;
    __nv_bfloat16* qn_h = act + 2 * SBUF; __nv_bfloat16* qn_l = act + 3 * SBUF;
    __nv_bfloat16* o_h  = act + 2 * SBUF; __nv_bfloat16* o_l  = act + 3 * SBUF;  // overlay qn
    __nv_bfloat16* in_h = act + 4 * SBUF; __nv_bfloat16* in_l = act + 5 * SBUF;
    __nv_bfloat16* x2_h = act + 0 * SBUF; __nv_bfloat16* x2_l = act + 1 * SBUF;  // overlay xn
    __nv_bfloat16* h_h  = act + 2 * SBUF; __nv_bfloat16* h_l  = act + 4 * SBUF;  // half-token h

    const size_t OWQ1 = 0,        OWKV1 = 262144,  OWO1 = 786432;
    const size_t OWQ2 = 1048576,  OWKV2 = 1310720, OWO2 = 1835008;
    const size_t OW1  = 2097152,  OW2   = 3145728;
    __nv_bfloat16* wh = wt;  __nv_bfloat16* wl = wt + WTOT;

    cudaFuncSetAttribute(gemm_bf<0,2>, cudaFuncAttributeMaxDynamicSharedMemorySize, GEMM_SMEM);
    cudaFuncSetAttribute(gemm_bf<3,1>, cudaFuncAttributeMaxDynamicSharedMemorySize, GEMM_SMEM);
    cudaFuncSetAttribute(gemm_bf<2,2>, cudaFuncAttributeMaxDynamicSharedMemorySize, GEMM_SMEM);
    cudaFuncSetAttribute(gemm_bf<3,0>, cudaFuncAttributeMaxDynamicSharedMemorySize, GEMM_SMEM);
    cudaFuncSetAttribute(attn_fa,      cudaFuncAttributeMaxDynamicSharedMemorySize, FA_SMEM);

    CvtArgs ca;
    ca.s[0]=a1_Wq; ca.s[1]=a1_Wkv; ca.s[2]=a1_Wo; ca.s[3]=a2_Wq;
    ca.s[4]=a2_Wkv; ca.s[5]=a2_Wo; ca.s[6]=ff_W1; ca.s[7]=ff_W2;
    cvt_all<<<4096, 256>>>(ca, wh, wl);

    const dim3 gN512 (4,  NTOK/BM);
    const dim3 gN1024(8,  NTOK/BM);
    const dim3 attng(G_, HEADS_, 2);

    group_ln_k<0><<<G_, 512>>>(x,       ln_seq_w, ln_seq_b, nullptr, xn_h, xn_l);
    group_ln_k<0><<<G_, 512>>>(queries, ln_q_w,   ln_q_b,   nullptr, qn_h, qn_l);

    // Attention 1: induced = attn(ln(queries), ln(x))
    gemm_bf<0,2><<<gN512,  256, GEMM_SMEM>>>(qn_h, qn_l, wh+OWQ1,  wl+OWQ1,  nullptr, nullptr,
                                             nullptr, q_h, q_l, NTOK, DIMM,   DIMM);
    gemm_bf<0,2><<<gN1024, 256, GEMM_SMEM>>>(xn_h, xn_l, wh+OWKV1, wl+OWKV1, nullptr, nullptr,
                                             nullptr, kv_h, kv_l, NTOK, 2*DIMM, DIMM);
    attn_fa<<<attng, 256, FA_SMEM>>>(q_h, q_l, kv_h, kv_l, o_h, o_l);
    // induced pair -> in ; q2 = induced + queries -> out_q (fused)
    gemm_bf<3,1><<<gN512,  256, GEMM_SMEM>>>(o_h, o_l, wh+OWO1, wl+OWO1, a1_bo, queries,
                                             out_q, in_h, in_l, NTOK, DIMM, DIMM);

    // Attention 2: out = attn(ln(x), induced); x2 = out + x (fused)
    gemm_bf<0,2><<<gN512,  256, GEMM_SMEM>>>(xn_h, xn_l, wh+OWQ2,  wl+OWQ2,  nullptr, nullptr,
                                             nullptr, q_h, q_l, NTOK, DIMM,   DIMM);
    gemm_bf<0,2><<<gN1024, 256, GEMM_SMEM>>>(in_h, in_l, wh+OWKV2, wl+OWKV2, nullptr, nullptr,
                                             nullptr, kv_h, kv_l, NTOK, 2*DIMM, DIMM);
    attn_fa<<<attng, 256, FA_SMEM>>>(q_h, q_l, kv_h, kv_l, o_h, o_l);
    gemm_bf<3,0><<<gN512,  256, GEMM_SMEM>>>(o_h, o_l, wh+OWO2, wl+OWO2, a2_bo, x,
                                             p_x2, nullptr, nullptr, NTOK, DIMM, DIMM);

    // FF block: LN, then two M-halves through the h pair buffer
    group_ln_k<1><<<G_, 512>>>(p_x2, ff_ln_w, ff_ln_b, p_xn2, x2_h, x2_l);

    const int MH = NTOK / 2;
    const dim3 gFF1(4 * DIMM / BN, MH / BM);
    const dim3 gFF2(DIMM / BN,     MH / BM);
    for (int half = 0; half < 2; half++) {
        const size_t aoff = (size_t)half * MH * DIMM;
        gemm_bf<2,2><<<gFF1, 256, GEMM_SMEM>>>(x2_h + aoff, x2_l + aoff, wh+OW1, wl+OW1,
                                               ff_b1, nullptr,
                                               nullptr, h_h, h_l, MH, 4*DIMM, DIMM);
        gemm_bf<3,0><<<gFF2, 256, GEMM_SMEM>>>(h_h, h_l, wh+OW2, wl+OW2,
                                               ff_b2, p_xn2 + aoff,
                                               out_x + aoff, nullptr, nullptr,
                                               MH, DIMM, 4*DIMM);
    }
}